// round 14
// baseline (speedup 1.0000x reference)
#include <cuda_runtime.h>
#include <cuda_fp16.h>
#include <cstdint>
#include <cstring>

#define N_OBJ 50000
#define N_REL 200000
#define FEAT 1024
#define INTER 512
#define EMB 200
#define N_CLS 151
#define N_PRED 51

typedef __half half_t;

// ---------------- scratch ----------------
__device__ half_t g_h1r_h[(size_t)N_REL * INTER];
__device__ half_t g_h1o_h[(size_t)N_OBJ * INTER];
__device__ half_t g_pri_h[(size_t)N_REL * EMB];
__device__ half_t g_soi_h[(size_t)N_OBJ * EMB];
__device__ half_t g_paf_h[(size_t)N_REL * EMB];
__device__ half_t g_soo_h[(size_t)N_OBJ * EMB];
__device__ half_t g_hpo_h[(size_t)N_REL * EMB];
__device__ half_t g_pe_h[N_PRED * EMB];
__device__ half_t g_oe_h[N_CLS * EMB];
// fp16 weights
__device__ half_t g_wrs[EMB * EMB];
__device__ half_t g_wos[EMB * EMB];
__device__ half_t g_wso1[INTER * FEAT];
__device__ half_t g_wso2[EMB * INTER];
__device__ half_t g_wsoo[EMB * EMB];
__device__ half_t g_wp1[INTER * FEAT];
__device__ half_t g_wp2[EMB * INTER];
__device__ half_t g_wpip[EMB * EMB];
__device__ half_t g_wcmb[EMB * EMB];
__device__ half_t g_w1s[EMB * EMB];
__device__ half_t g_w1p[EMB * EMB];
__device__ half_t g_w1o[EMB * EMB];
__device__ half_t g_wpo2[EMB * EMB];
// fp32 intermediates
__device__ float g_Acomb[(size_t)N_OBJ * EMB];
__device__ float g_tmpP[(size_t)N_REL * EMB];
__device__ float g_Bs[(size_t)N_OBJ * EMB];
__device__ float g_Bo[(size_t)N_OBJ * EMB];
__device__ float g_tmpQ[(size_t)N_REL * EMB];

// ---------------- device helpers ----------------
__device__ __forceinline__ uint32_t smem_u32(const void* p) {
    uint32_t a;
    asm("{ .reg .u64 t; cvta.to.shared.u64 t, %1; cvt.u32.u64 %0, t; }" : "=r"(a) : "l"(p));
    return a;
}

__device__ __forceinline__ void ldsm_x4(uint32_t& r0, uint32_t& r1, uint32_t& r2, uint32_t& r3,
                                        uint32_t addr) {
    asm volatile("ldmatrix.sync.aligned.m8n8.x4.shared.b16 {%0,%1,%2,%3}, [%4];"
                 : "=r"(r0), "=r"(r1), "=r"(r2), "=r"(r3) : "r"(addr));
}

__device__ __forceinline__ void mma_f16(float* c, const uint32_t* a, uint32_t b0, uint32_t b1) {
    asm volatile("mma.sync.aligned.m16n8k16.row.col.f32.f16.f16.f32 "
                 "{%0,%1,%2,%3}, {%4,%5,%6,%7}, {%8,%9}, {%0,%1,%2,%3};"
                 : "+f"(c[0]), "+f"(c[1]), "+f"(c[2]), "+f"(c[3])
                 : "r"(a[0]), "r"(a[1]), "r"(a[2]), "r"(a[3]), "r"(b0), "r"(b1));
}

__device__ __forceinline__ void cp16(uint32_t dst, const void* src, bool valid) {
    int sz = valid ? 16 : 0;
    asm volatile("cp.async.cg.shared.global [%0], [%1], 16, %2;"
                 :: "r"(dst), "l"(src), "r"(sz) : "memory");
}
#define CP_COMMIT() asm volatile("cp.async.commit_group;" ::: "memory")
#define CP_WAIT1()  asm volatile("cp.async.wait_group 1;" ::: "memory")

__device__ __forceinline__ uint32_t pack_h2(float x, float y) {
    __half2 h = __floats2half2_rn(x, y);
    uint32_t u; memcpy(&u, &h, 4); return u;
}

// ---------------- fp16 GEMM: C = act(A @ W^T + bias) ----------
// CTA 128x128, BK=32, 8 warps (4M x 2N). AF32: A fp32 converted on STS.
// TAIL=1 used ONLY for the final N-tile launch (n0base offset); TAIL=0 body
// is branch-free and identical to the R8 mainloop.
#define ROWB 80
#define TILE_B (128 * ROWB)
#define STAGE_B (2 * TILE_B)
#define SMEM_TOT (2 * STAGE_B)   // 40960

template<int AF32, int TAIL>
__global__ __launch_bounds__(256, 2)
void hmma_h(const void* __restrict__ Av, const half_t* __restrict__ W,
            const float* __restrict__ bias,
            float* __restrict__ C, half_t* __restrict__ Ch,
            int M, int N, int K, int relu, int wf32, int wf16, int hbias, int n0base)
{
    extern __shared__ __align__(16) char smem[];
    const uint32_t base = smem_u32(smem);

    const int tid = threadIdx.x;
    const int lane = tid & 31;
    const int wid = tid >> 5;
    const int wm = wid & 3;
    const int wn = wid >> 2;
    const int m0 = blockIdx.y * 128;
    const int n0 = n0base + blockIdx.x * 128;
    const int nlim = N - n0 - wn * 64;

    const int lrA = (lane & 7) + ((lane >> 3) & 1) * 8;
    const int wA  = lane >> 4;
    const int lrB = (lane & 7) + ((lane >> 4) << 3);
    const int wB  = (lane >> 3) & 1;
    const int gid = lane >> 2, tig = lane & 3;

    float c[2][8][4];
#pragma unroll
    for (int i = 0; i < 2; i++)
#pragma unroll
        for (int j = 0; j < 8; j++)
#pragma unroll
            for (int q = 0; q < 4; q++) c[i][j][q] = 0.f;

    const int nkb = (K + 31) >> 5;
    const float* A32 = (const float*)Av;
    const half_t* A16 = (const half_t*)Av;

    float4 ra[4];

    auto prefetch_a32 = [&](int k0) {
#pragma unroll
        for (int i = 0; i < 4; i++) {
            int idx = tid + i * 256;
            int r = idx >> 3, c4 = idx & 7, gk = k0 + c4 * 4;
            bool v = (m0 + r < M) && (gk < K);
            int rr = (m0 + r < M) ? (m0 + r) : 0;
            ra[i] = v ? *(const float4*)(A32 + (size_t)rr * K + (gk < K ? gk : 0))
                      : make_float4(0.f, 0.f, 0.f, 0.f);
        }
    };
    auto sts_a32 = [&](int stage) {
        const uint32_t stg = base + (uint32_t)stage * STAGE_B;
#pragma unroll
        for (int i = 0; i < 4; i++) {
            int idx = tid + i * 256;
            int r = idx >> 3, c4 = idx & 7;
            uint32_t h0 = pack_h2(ra[i].x, ra[i].y);
            uint32_t h1 = pack_h2(ra[i].z, ra[i].w);
            uint32_t dst = stg + (uint32_t)(r * ROWB + c4 * 8);
            asm volatile("st.shared.v2.b32 [%0], {%1, %2};"
                         :: "r"(dst), "r"(h0), "r"(h1) : "memory");
        }
    };
    auto cp_w = [&](int stage, int k0) {
        const uint32_t stg = base + (uint32_t)stage * STAGE_B + TILE_B;
#pragma unroll
        for (int i = 0; i < 2; i++) {
            int idx = tid + i * 256;
            int ch = idx & 3, r = idx >> 2;
            uint32_t dst = stg + (uint32_t)(r * ROWB + ch * 16);
            int ke = k0 + ch * 8;
            bool v = (n0 + r < N) && (ke < K);
            int rr = (n0 + r < N) ? (n0 + r) : 0;
            cp16(dst, W + (size_t)rr * K + (ke < K ? ke : 0), v);
        }
    };
    auto cp_aw16 = [&](int stage, int k0) {
        const uint32_t stg = base + (uint32_t)stage * STAGE_B;
#pragma unroll
        for (int i = 0; i < 4; i++) {
            int idx = tid + i * 256;
            int ch = idx & 3;
            int r  = (idx >> 2) & 127;
            int t2 = idx >> 9;
            uint32_t dst = stg + (uint32_t)t2 * TILE_B + (uint32_t)(r * ROWB + ch * 16);
            int ke = k0 + ch * 8;
            const half_t* sp;
            bool v;
            if (t2 == 0) {
                v = (m0 + r < M) && (ke < K);
                int rr = (m0 + r < M) ? (m0 + r) : 0;
                sp = A16 + (size_t)rr * K + (ke < K ? ke : 0);
            } else {
                v = (n0 + r < N) && (ke < K);
                int rr = (n0 + r < N) ? (n0 + r) : 0;
                sp = W + (size_t)rr * K + (ke < K ? ke : 0);
            }
            cp16(dst, sp, v);
        }
    };

    if (AF32) { prefetch_a32(0); cp_w(0, 0); }
    else      { cp_aw16(0, 0); }
    CP_COMMIT();

    for (int kb = 0; kb < nkb; kb++) {
        const int s = kb & 1;
        if (AF32) {
            if (kb + 1 < nkb) cp_w(s ^ 1, (kb + 1) << 5);
            CP_COMMIT();
            CP_WAIT1();
            sts_a32(s);
            __syncthreads();
            if (kb + 1 < nkb) prefetch_a32((kb + 1) << 5);
        } else {
            if (kb + 1 < nkb) cp_aw16(s ^ 1, (kb + 1) << 5);
            CP_COMMIT();
            CP_WAIT1();
            __syncthreads();
        }

        const uint32_t stg = base + (uint32_t)s * STAGE_B;
        const uint32_t sA = stg, sB = stg + TILE_B;

#pragma unroll
        for (int kc = 0; kc < 2; kc++) {
            const uint32_t acol = (uint32_t)((2 * kc + wA) * 16);
            const uint32_t bcol = (uint32_t)((2 * kc + wB) * 16);
            uint32_t a[2][4];
#pragma unroll
            for (int mt = 0; mt < 2; mt++) {
                uint32_t ro = (uint32_t)((wm * 32 + mt * 16 + lrA) * ROWB);
                ldsm_x4(a[mt][0], a[mt][1], a[mt][2], a[mt][3], sA + ro + acol);
            }
            uint32_t b[4][4];
#pragma unroll
            for (int nt4 = 0; nt4 < 4; nt4++) {
                if (!TAIL || nt4 * 16 < nlim) {
                    uint32_t ro = (uint32_t)((wn * 64 + nt4 * 16 + lrB) * ROWB);
                    ldsm_x4(b[nt4][0], b[nt4][1], b[nt4][2], b[nt4][3], sB + ro + bcol);
                }
            }
#pragma unroll
            for (int mt = 0; mt < 2; mt++)
#pragma unroll
                for (int nt = 0; nt < 8; nt++) {
                    if (!TAIL || nt * 8 < nlim) {
                        const int nn = nt >> 1, oc = (nt & 1) * 2;
                        mma_f16(c[mt][nt], a[mt], b[nn][oc], b[nn][oc + 1]);
                    }
                }
        }
        __syncthreads();
    }

    // epilogue
#pragma unroll
    for (int nt = 0; nt < 8; nt++) {
        const int col = n0 + wn * 64 + nt * 8 + tig * 2;
        if (col >= N) continue;
        float2 bb = make_float2(0.f, 0.f);
        if (hbias) bb = *(const float2*)(bias + col);
#pragma unroll
        for (int mt = 0; mt < 2; mt++) {
            const int r0 = m0 + wm * 32 + mt * 16 + gid;
            float v0 = c[mt][nt][0] + bb.x, v1 = c[mt][nt][1] + bb.y;
            float v2 = c[mt][nt][2] + bb.x, v3 = c[mt][nt][3] + bb.y;
            if (relu) {
                v0 = fmaxf(v0, 0.f); v1 = fmaxf(v1, 0.f);
                v2 = fmaxf(v2, 0.f); v3 = fmaxf(v3, 0.f);
            }
            if (r0 < M) {
                size_t o = (size_t)r0 * N + col;
                if (wf32) *(float2*)(C + o) = make_float2(v0, v1);
                if (wf16) *(uint32_t*)(Ch + o) = pack_h2(v0, v1);
            }
            if (r0 + 8 < M) {
                size_t o = (size_t)(r0 + 8) * N + col;
                if (wf32) *(float2*)(C + o) = make_float2(v2, v3);
                if (wf16) *(uint32_t*)(Ch + o) = pack_h2(v2, v3);
            }
        }
    }
}

// ---------------- batched weight/activation conversion ----------------
#define NSEG 15
struct ConvSeg { const float* src; half_t* dst; int lds; int K; int off; };
struct ConvArgs { ConvSeg seg[NSEG]; int nseg; int total; };

__global__ void conv_all(ConvArgs a)
{
    int t = blockIdx.x * blockDim.x + threadIdx.x;
    if (t >= a.total) return;
    int i = 0;
#pragma unroll
    for (int j = 1; j < NSEG; j++)
        if (j < a.nseg && t >= a.seg[j].off) i = j;
    const ConvSeg s = a.seg[i];
    int l = t - s.off;
    int r = l / s.K, cc = l % s.K;
    s.dst[l] = __float2half_rn(s.src[(size_t)r * s.lds + cc]);
}

__global__ void combine_wpi_h(const float* __restrict__ Wpi, half_t* __restrict__ dst)
{
    int t = blockIdx.x * blockDim.x + threadIdx.x;
    if (t >= EMB * EMB) return;
    int r = t / EMB, cc = t % EMB;
    dst[t] = __float2half_rn(Wpi[r * 600 + cc] + Wpi[r * 600 + 400 + cc]);
}

__global__ void gather_rows_f4(const float* __restrict__ src, const int* __restrict__ idx,
                               float* __restrict__ dst, int nrows)
{
    const int C4 = EMB / 4;
    int t = blockIdx.x * blockDim.x + threadIdx.x;
    if (t >= nrows * C4) return;
    int r = t / C4, cc = t % C4;
    ((float4*)dst)[t] = ((const float4*)src)[(size_t)idx[r] * C4 + cc];
}

__global__ void fuse_pi_h(const float* __restrict__ tmpP, const float* __restrict__ Acomb,
                          const int* __restrict__ rel_inds, const float* __restrict__ bias,
                          uint32_t* __restrict__ outh)
{
    const int C4 = EMB / 4;
    int t = blockIdx.x * blockDim.x + threadIdx.x;
    if (t >= N_REL * C4) return;
    int r = t / C4, cc = t % C4;
    int s = rel_inds[r * 3 + 1];
    float4 p = ((const float4*)tmpP)[t];
    float4 a = ((const float4*)Acomb)[(size_t)s * C4 + cc];
    float4 b = ((const float4*)bias)[cc];
    float v0 = fmaxf(p.x + a.x + b.x, 0.f), v1 = fmaxf(p.y + a.y + b.y, 0.f);
    float v2 = fmaxf(p.z + a.z + b.z, 0.f), v3 = fmaxf(p.w + a.w + b.w, 0.f);
    outh[t * 2]     = pack_h2(v0, v1);
    outh[t * 2 + 1] = pack_h2(v2, v3);
}

__global__ void fuse_po_h(const float* __restrict__ tmpQ, const float* __restrict__ Bsub,
                          const float* __restrict__ Bobj, const int* __restrict__ rel_inds,
                          const float* __restrict__ bias, uint32_t* __restrict__ outh)
{
    const int C4 = EMB / 4;
    int t = blockIdx.x * blockDim.x + threadIdx.x;
    if (t >= N_REL * C4) return;
    int r = t / C4, cc = t % C4;
    int s = rel_inds[r * 3 + 1];
    int o = rel_inds[r * 3 + 2];
    float4 q  = ((const float4*)tmpQ)[t];
    float4 bs = ((const float4*)Bsub)[(size_t)s * C4 + cc];
    float4 bo = ((const float4*)Bobj)[(size_t)o * C4 + cc];
    float4 b  = ((const float4*)bias)[cc];
    float v0 = fmaxf(q.x + bs.x + bo.x + b.x, 0.f), v1 = fmaxf(q.y + bs.y + bo.y + b.y, 0.f);
    float v2 = fmaxf(q.z + bs.z + bo.z + b.z, 0.f), v3 = fmaxf(q.w + bs.w + bo.w + b.w, 0.f);
    outh[t * 2]     = pack_h2(v0, v1);
    outh[t * 2 + 1] = pack_h2(v2, v3);
}

// ---------------- host side ----------------
template <typename T>
static T* sym(const void* s)
{
    void* p = nullptr;
    cudaGetSymbolAddress(&p, s);
    return (T*)p;
}

static void set_attrs()
{
    static bool done = false;
    if (!done) {
        cudaFuncSetAttribute(hmma_h<0,0>, cudaFuncAttributeMaxDynamicSharedMemorySize, SMEM_TOT);
        cudaFuncSetAttribute(hmma_h<0,1>, cudaFuncAttributeMaxDynamicSharedMemorySize, SMEM_TOT);
        cudaFuncSetAttribute(hmma_h<1,0>, cudaFuncAttributeMaxDynamicSharedMemorySize, SMEM_TOT);
        done = true;
    }
}

static void gemmh(const half_t* A, const half_t* W, const float* bias,
                  float* C, half_t* Ch, int M, int N, int K, bool relu)
{
    set_attrs();
    const int mt = (M + 127) / 128;
    const int nfull = N / 128;
    dim3 block(256);
    if (nfull > 0) {
        dim3 grid(nfull, mt);
        hmma_h<0,0><<<grid, block, SMEM_TOT>>>(A, W, bias, C, Ch, M, N, K,
                                               relu ? 1 : 0, C ? 1 : 0, Ch ? 1 : 0,
                                               bias ? 1 : 0, 0);
    }
    if (N % 128) {
        dim3 grid(1, mt);
        hmma_h<0,1><<<grid, block, SMEM_TOT>>>(A, W, bias, C, Ch, M, N, K,
                                               relu ? 1 : 0, C ? 1 : 0, Ch ? 1 : 0,
                                               bias ? 1 : 0, nfull * 128);
    }
}

static void gemmh32(const float* A, const half_t* W, const float* bias,
                    float* C, half_t* Ch, int M, int N, int K, bool relu)
{
    set_attrs();
    dim3 grid(N / 128, (M + 127) / 128), block(256);
    hmma_h<1,0><<<grid, block, SMEM_TOT>>>(A, W, bias, C, Ch, M, N, K,
                                           relu ? 1 : 0, C ? 1 : 0, Ch ? 1 : 0,
                                           bias ? 1 : 0, 0);
}

extern "C" void kernel_launch(void* const* d_in, const int* in_sizes, int n_in,
                              void* d_out, int out_size)
{
    (void)in_sizes; (void)n_in; (void)out_size;

    const float* obj_feats  = (const float*)d_in[1];
    const float* rel_feats  = (const float*)d_in[2];
    const int*   rel_inds   = (const int*)d_in[4];
    const int*   gt_rel     = (const int*)d_in[5];
    const int*   gt_obj     = (const int*)d_in[6];
    const float* obj_embed  = (const float*)d_in[7];
    const float* pred_embed = (const float*)d_in[8];
    const float* Wrs = (const float*)d_in[9];  const float* brs = (const float*)d_in[10];
    const float* Wos = (const float*)d_in[11]; const float* bos = (const float*)d_in[12];
    const float* Wso1= (const float*)d_in[13]; const float* bso1= (const float*)d_in[14];
    const float* Wso2= (const float*)d_in[15]; const float* bso2= (const float*)d_in[16];
    const float* Wsoo= (const float*)d_in[17]; const float* bsoo= (const float*)d_in[18];
    const float* Wp1 = (const float*)d_in[19]; const float* bp1 = (const float*)d_in[20];
    const float* Wp2 = (const float*)d_in[21]; const float* bp2 = (const float*)d_in[22];
    const float* Wpi = (const float*)d_in[23]; const float* bpi = (const float*)d_in[24];
    const float* Wpo1= (const float*)d_in[25]; const float* bpo1= (const float*)d_in[26];
    const float* Wpo2= (const float*)d_in[27]; const float* bpo2= (const float*)d_in[28];

    float* out = (float*)d_out;
    float* o_so_out   = out;                      // [50000,200]
    float* o_pred_out = out + 10000000;           // [200000,200]
    float* o_rel_sem  = out + 50000000;           // [200000,200]
    float* o_obj_sem  = out + 90000000;           // [50000,200]
    float* o_rel_gt   = out + 100000000;          // [51,200]
    float* o_obj_gt   = out + 100010200;          // [151,200]

    half_t *h1r = sym<half_t>(g_h1r_h), *h1o = sym<half_t>(g_h1o_h);
    half_t *pri = sym<half_t>(g_pri_h), *soi = sym<half_t>(g_soi_h);
    half_t *paf = sym<half_t>(g_paf_h), *soo = sym<half_t>(g_soo_h);
    half_t *hpo = sym<half_t>(g_hpo_h);
    half_t *pe = sym<half_t>(g_pe_h), *oe = sym<half_t>(g_oe_h);
    half_t *wrs = sym<half_t>(g_wrs), *wos = sym<half_t>(g_wos);
    half_t *wso1 = sym<half_t>(g_wso1), *wso2 = sym<half_t>(g_wso2);
    half_t *wsoo = sym<half_t>(g_wsoo);
    half_t *wp1 = sym<half_t>(g_wp1), *wp2 = sym<half_t>(g_wp2);
    half_t *wpip = sym<half_t>(g_wpip), *wcmb = sym<half_t>(g_wcmb);
    half_t *w1s = sym<half_t>(g_w1s), *w1p = sym<half_t>(g_w1p), *w1o = sym<half_t>(g_w1o);
    half_t *wpo2 = sym<half_t>(g_wpo2);
    float *Acomb = sym<float>(g_Acomb), *tmpP = sym<float>(g_tmpP);
    float *Bs = sym<float>(g_Bs), *Bo = sym<float>(g_Bo), *tmpQ = sym<float>(g_tmpQ);

    // ---- one batched conversion for all weights + embeds ----
    {
        ConvArgs a;
        int off = 0, i = 0;
        auto add = [&](const float* src, half_t* dst, int lds, int N, int K) {
            a.seg[i].src = src; a.seg[i].dst = dst; a.seg[i].lds = lds;
            a.seg[i].K = K; a.seg[i].off = off;
            off += N * K; i++;
        };
        add(Wrs, wrs, EMB, EMB, EMB);
        add(Wos, wos, EMB, EMB, EMB);
        add(Wso1, wso1, FEAT, INTER, FEAT);
        add(Wso2, wso2, INTER, EMB, INTER);
        add(Wsoo, wsoo, EMB, EMB, EMB);
        add(Wp1, wp1, FEAT, INTER, FEAT);
        add(Wp2, wp2, INTER, EMB, INTER);
        add(Wpi + EMB, wpip, 600, EMB, EMB);
        add(Wpo1, w1s, 600, EMB, EMB);
        add(Wpo1 + EMB, w1p, 600, EMB, EMB);
        add(Wpo1 + 2 * EMB, w1o, 600, EMB, EMB);
        add(Wpo2, wpo2, EMB, EMB, EMB);
        add(pred_embed, pe, EMB, N_PRED, EMB);
        add(obj_embed, oe, EMB, N_CLS, EMB);
        a.nseg = i; a.total = off;
        conv_all<<<(off + 255) / 256, 256>>>(a);
    }
    combine_wpi_h<<<(EMB * EMB + 255) / 256, 256>>>(Wpi, wcmb);

    // ---- semantic tables + gathers ----
    gemmh(pe, wrs, brs, o_rel_gt, nullptr, N_PRED, EMB, EMB, false);
    gemmh(oe, wos, bos, o_obj_gt, nullptr, N_CLS, EMB, EMB, false);
    gather_rows_f4<<<(N_REL * (EMB / 4) + 255) / 256, 256>>>(o_rel_gt, gt_rel, o_rel_sem, N_REL);
    gather_rows_f4<<<(N_OBJ * (EMB / 4) + 255) / 256, 256>>>(o_obj_gt, gt_obj, o_obj_sem, N_OBJ);

    // ---- object path ----
    gemmh32(obj_feats, wso1, bso1, nullptr, h1o, N_OBJ, INTER, FEAT, true);
    gemmh(h1o, wso2, bso2, nullptr, soi, N_OBJ, EMB, INTER, true);
    gemmh(soi, wsoo, bsoo, o_so_out, soo, N_OBJ, EMB, EMB, false);

    // ---- relation path ----
    gemmh32(rel_feats, wp1, bp1, nullptr, h1r, N_REL, INTER, FEAT, true);
    gemmh(h1r, wp2, bp2, nullptr, pri, N_REL, EMB, INTER, true);

    // ---- pred_inter_af (factored concat; obj slice == sub slice index) ----
    gemmh(soi, wcmb, nullptr, Acomb, nullptr, N_OBJ, EMB, EMB, false);
    gemmh(pri, wpip, nullptr, tmpP, nullptr, N_REL, EMB, EMB, false);
    fuse_pi_h<<<(N_REL * (EMB / 4) + 255) / 256, 256>>>(tmpP, Acomb, rel_inds, bpi,
                                                        (uint32_t*)paf);

    // ---- pred_out (factored concat) ----
    gemmh(soo, w1s, nullptr, Bs, nullptr, N_OBJ, EMB, EMB, false);
    gemmh(soo, w1o, nullptr, Bo, nullptr, N_OBJ, EMB, EMB, false);
    gemmh(paf, w1p, nullptr, tmpQ, nullptr, N_REL, EMB, EMB, false);
    fuse_po_h<<<(N_REL * (EMB / 4) + 255) / 256, 256>>>(tmpQ, Bs, Bo, rel_inds, bpo1,
                                                        (uint32_t*)hpo);
    gemmh(hpo, wpo2, bpo2, o_pred_out, nullptr, N_REL, EMB, EMB, false);
}

// round 16
// speedup vs baseline: 1.1019x; 1.1019x over previous
#include <cuda_runtime.h>
#include <cuda_fp16.h>
#include <cstdint>
#include <cstring>

#define N_OBJ 50000
#define N_REL 200000
#define FEAT 1024
#define INTER 512
#define EMB 200
#define N_CLS 151
#define N_PRED 51

typedef __half half_t;

// ---------------- scratch ----------------
__device__ half_t g_h1r_h[(size_t)N_REL * INTER];
__device__ half_t g_h1o_h[(size_t)N_OBJ * INTER];
__device__ half_t g_pri_h[(size_t)N_REL * EMB];
__device__ half_t g_soi_h[(size_t)N_OBJ * EMB];
__device__ half_t g_paf_h[(size_t)N_REL * EMB];
__device__ half_t g_soo_h[(size_t)N_OBJ * EMB];
__device__ half_t g_hpo_h[(size_t)N_REL * EMB];
__device__ half_t g_pe_h[N_PRED * EMB];
__device__ half_t g_oe_h[N_CLS * EMB];
// fp16 weights
__device__ half_t g_wrs[EMB * EMB];
__device__ half_t g_wos[EMB * EMB];
__device__ half_t g_wso1[INTER * FEAT];
__device__ half_t g_wso2[EMB * INTER];
__device__ half_t g_wsoo[EMB * EMB];
__device__ half_t g_wp1[INTER * FEAT];
__device__ half_t g_wp2[EMB * INTER];
__device__ half_t g_wpip[EMB * EMB];
__device__ half_t g_wcmb[EMB * EMB];
__device__ half_t g_w1p[EMB * EMB];
__device__ half_t g_wBsBo[2 * EMB * EMB];  // rows 0..199: Wpo1[:,0:200]; rows 200..399: Wpo1[:,400:600]
__device__ half_t g_wpo2[EMB * EMB];
// fp32 intermediates
__device__ float g_Acomb[(size_t)N_OBJ * EMB];
__device__ float g_tmpP[(size_t)N_REL * EMB];
__device__ float g_BsBo[(size_t)N_OBJ * 2 * EMB];  // [M,400]: cols 0..199 = Bs, 200..399 = Bo
__device__ float g_tmpQ[(size_t)N_REL * EMB];

// ---------------- device helpers ----------------
__device__ __forceinline__ uint32_t smem_u32(const void* p) {
    uint32_t a;
    asm("{ .reg .u64 t; cvta.to.shared.u64 t, %1; cvt.u32.u64 %0, t; }" : "=r"(a) : "l"(p));
    return a;
}

__device__ __forceinline__ void ldsm_x4(uint32_t& r0, uint32_t& r1, uint32_t& r2, uint32_t& r3,
                                        uint32_t addr) {
    asm volatile("ldmatrix.sync.aligned.m8n8.x4.shared.b16 {%0,%1,%2,%3}, [%4];"
                 : "=r"(r0), "=r"(r1), "=r"(r2), "=r"(r3) : "r"(addr));
}

__device__ __forceinline__ void mma_f16(float* c, const uint32_t* a, uint32_t b0, uint32_t b1) {
    asm volatile("mma.sync.aligned.m16n8k16.row.col.f32.f16.f16.f32 "
                 "{%0,%1,%2,%3}, {%4,%5,%6,%7}, {%8,%9}, {%0,%1,%2,%3};"
                 : "+f"(c[0]), "+f"(c[1]), "+f"(c[2]), "+f"(c[3])
                 : "r"(a[0]), "r"(a[1]), "r"(a[2]), "r"(a[3]), "r"(b0), "r"(b1));
}

__device__ __forceinline__ void cp16(uint32_t dst, const void* src, bool valid) {
    int sz = valid ? 16 : 0;
    asm volatile("cp.async.cg.shared.global [%0], [%1], 16, %2;"
                 :: "r"(dst), "l"(src), "r"(sz) : "memory");
}
#define CP_COMMIT() asm volatile("cp.async.commit_group;" ::: "memory")
#define CP_WAIT1()  asm volatile("cp.async.wait_group 1;" ::: "memory")

__device__ __forceinline__ uint32_t pack_h2(float x, float y) {
    __half2 h = __floats2half2_rn(x, y);
    uint32_t u; memcpy(&u, &h, 4); return u;
}

// ---------------- fp16 GEMM: C = act(A @ W^T + bias) — R8 mainloop ----------
#define ROWB 80
#define TILE_B (128 * ROWB)
#define STAGE_B (2 * TILE_B)
#define SMEM_TOT (2 * STAGE_B)   // 40960

template<int AF32>
__global__ __launch_bounds__(256, 2)
void hmma_h(const void* __restrict__ Av, const half_t* __restrict__ W,
            const float* __restrict__ bias,
            float* __restrict__ C, half_t* __restrict__ Ch,
            int M, int N, int K, int relu, int wf32, int wf16, int hbias)
{
    extern __shared__ __align__(16) char smem[];
    const uint32_t base = smem_u32(smem);

    const int tid = threadIdx.x;
    const int lane = tid & 31;
    const int wid = tid >> 5;
    const int wm = wid & 3;
    const int wn = wid >> 2;
    const int m0 = blockIdx.y * 128;
    const int n0 = blockIdx.x * 128;

    const int lrA = (lane & 7) + ((lane >> 3) & 1) * 8;
    const int wA  = lane >> 4;
    const int lrB = (lane & 7) + ((lane >> 4) << 3);
    const int wB  = (lane >> 3) & 1;
    const int gid = lane >> 2, tig = lane & 3;

    float c[2][8][4];
#pragma unroll
    for (int i = 0; i < 2; i++)
#pragma unroll
        for (int j = 0; j < 8; j++)
#pragma unroll
            for (int q = 0; q < 4; q++) c[i][j][q] = 0.f;

    const int nkb = (K + 31) >> 5;
    const float* A32 = (const float*)Av;
    const half_t* A16 = (const half_t*)Av;

    float4 ra[4];

    auto prefetch_a32 = [&](int k0) {
#pragma unroll
        for (int i = 0; i < 4; i++) {
            int idx = tid + i * 256;
            int r = idx >> 3, c4 = idx & 7, gk = k0 + c4 * 4;
            bool v = (m0 + r < M) && (gk < K);
            int rr = (m0 + r < M) ? (m0 + r) : 0;
            ra[i] = v ? *(const float4*)(A32 + (size_t)rr * K + (gk < K ? gk : 0))
                      : make_float4(0.f, 0.f, 0.f, 0.f);
        }
    };
    auto sts_a32 = [&](int stage) {
        const uint32_t stg = base + (uint32_t)stage * STAGE_B;
#pragma unroll
        for (int i = 0; i < 4; i++) {
            int idx = tid + i * 256;
            int r = idx >> 3, c4 = idx & 7;
            uint32_t h0 = pack_h2(ra[i].x, ra[i].y);
            uint32_t h1 = pack_h2(ra[i].z, ra[i].w);
            uint32_t dst = stg + (uint32_t)(r * ROWB + c4 * 8);
            asm volatile("st.shared.v2.b32 [%0], {%1, %2};"
                         :: "r"(dst), "r"(h0), "r"(h1) : "memory");
        }
    };
    auto cp_w = [&](int stage, int k0) {
        const uint32_t stg = base + (uint32_t)stage * STAGE_B + TILE_B;
#pragma unroll
        for (int i = 0; i < 2; i++) {
            int idx = tid + i * 256;
            int ch = idx & 3, r = idx >> 2;
            uint32_t dst = stg + (uint32_t)(r * ROWB + ch * 16);
            int ke = k0 + ch * 8;
            bool v = (n0 + r < N) && (ke < K);
            int rr = (n0 + r < N) ? (n0 + r) : 0;
            cp16(dst, W + (size_t)rr * K + (ke < K ? ke : 0), v);
        }
    };
    auto cp_aw16 = [&](int stage, int k0) {
        const uint32_t stg = base + (uint32_t)stage * STAGE_B;
#pragma unroll
        for (int i = 0; i < 4; i++) {
            int idx = tid + i * 256;
            int ch = idx & 3;
            int r  = (idx >> 2) & 127;
            int t2 = idx >> 9;
            uint32_t dst = stg + (uint32_t)t2 * TILE_B + (uint32_t)(r * ROWB + ch * 16);
            int ke = k0 + ch * 8;
            const half_t* sp;
            bool v;
            if (t2 == 0) {
                v = (m0 + r < M) && (ke < K);
                int rr = (m0 + r < M) ? (m0 + r) : 0;
                sp = A16 + (size_t)rr * K + (ke < K ? ke : 0);
            } else {
                v = (n0 + r < N) && (ke < K);
                int rr = (n0 + r < N) ? (n0 + r) : 0;
                sp = W + (size_t)rr * K + (ke < K ? ke : 0);
            }
            cp16(dst, sp, v);
        }
    };

    if (AF32) { prefetch_a32(0); cp_w(0, 0); }
    else      { cp_aw16(0, 0); }
    CP_COMMIT();

    for (int kb = 0; kb < nkb; kb++) {
        const int s = kb & 1;
        if (AF32) {
            if (kb + 1 < nkb) cp_w(s ^ 1, (kb + 1) << 5);
            CP_COMMIT();
            CP_WAIT1();
            sts_a32(s);
            __syncthreads();
            if (kb + 1 < nkb) prefetch_a32((kb + 1) << 5);
        } else {
            if (kb + 1 < nkb) cp_aw16(s ^ 1, (kb + 1) << 5);
            CP_COMMIT();
            CP_WAIT1();
            __syncthreads();
        }

        const uint32_t stg = base + (uint32_t)s * STAGE_B;
        const uint32_t sA = stg, sB = stg + TILE_B;

#pragma unroll
        for (int kc = 0; kc < 2; kc++) {
            const uint32_t acol = (uint32_t)((2 * kc + wA) * 16);
            const uint32_t bcol = (uint32_t)((2 * kc + wB) * 16);
            uint32_t a[2][4];
#pragma unroll
            for (int mt = 0; mt < 2; mt++) {
                uint32_t ro = (uint32_t)((wm * 32 + mt * 16 + lrA) * ROWB);
                ldsm_x4(a[mt][0], a[mt][1], a[mt][2], a[mt][3], sA + ro + acol);
            }
            uint32_t b[4][4];
#pragma unroll
            for (int nt = 0; nt < 4; nt++) {
                uint32_t ro = (uint32_t)((wn * 64 + nt * 16 + lrB) * ROWB);
                ldsm_x4(b[nt][0], b[nt][1], b[nt][2], b[nt][3], sB + ro + bcol);
            }
#pragma unroll
            for (int mt = 0; mt < 2; mt++)
#pragma unroll
                for (int nt = 0; nt < 8; nt++) {
                    const int nn = nt >> 1, oc = (nt & 1) * 2;
                    mma_f16(c[mt][nt], a[mt], b[nn][oc], b[nn][oc + 1]);
                }
        }
        __syncthreads();
    }

    // epilogue
#pragma unroll
    for (int nt = 0; nt < 8; nt++) {
        const int col = n0 + wn * 64 + nt * 8 + tig * 2;
        if (col >= N) continue;
        float2 bb = make_float2(0.f, 0.f);
        if (hbias) bb = *(const float2*)(bias + col);
#pragma unroll
        for (int mt = 0; mt < 2; mt++) {
            const int r0 = m0 + wm * 32 + mt * 16 + gid;
            float v0 = c[mt][nt][0] + bb.x, v1 = c[mt][nt][1] + bb.y;
            float v2 = c[mt][nt][2] + bb.x, v3 = c[mt][nt][3] + bb.y;
            if (relu) {
                v0 = fmaxf(v0, 0.f); v1 = fmaxf(v1, 0.f);
                v2 = fmaxf(v2, 0.f); v3 = fmaxf(v3, 0.f);
            }
            if (r0 < M) {
                size_t o = (size_t)r0 * N + col;
                if (wf32) *(float2*)(C + o) = make_float2(v0, v1);
                if (wf16) *(uint32_t*)(Ch + o) = pack_h2(v0, v1);
            }
            if (r0 + 8 < M) {
                size_t o = (size_t)(r0 + 8) * N + col;
                if (wf32) *(float2*)(C + o) = make_float2(v2, v3);
                if (wf16) *(uint32_t*)(Ch + o) = pack_h2(v2, v3);
            }
        }
    }
}

// ---------------- batched weight/activation conversion ----------------
#define NSEG 16
struct ConvSeg { const float* src; half_t* dst; int lds; int K; int off; };
struct ConvArgs { ConvSeg seg[NSEG]; int nseg; int total; };

__global__ void conv_all(ConvArgs a)
{
    int t = blockIdx.x * blockDim.x + threadIdx.x;
    if (t >= a.total) return;
    int i = 0;
#pragma unroll
    for (int j = 1; j < NSEG; j++)
        if (j < a.nseg && t >= a.seg[j].off) i = j;
    const ConvSeg s = a.seg[i];
    int l = t - s.off;
    int r = l / s.K, cc = l % s.K;
    s.dst[l] = __float2half_rn(s.src[(size_t)r * s.lds + cc]);
}

__global__ void combine_wpi_h(const float* __restrict__ Wpi, half_t* __restrict__ dst)
{
    int t = blockIdx.x * blockDim.x + threadIdx.x;
    if (t >= EMB * EMB) return;
    int r = t / EMB, cc = t % EMB;
    dst[t] = __float2half_rn(Wpi[r * 600 + cc] + Wpi[r * 600 + 400 + cc]);
}

__global__ void gather_rows_f4(const float* __restrict__ src, const int* __restrict__ idx,
                               float* __restrict__ dst, int nrows)
{
    const int C4 = EMB / 4;
    int t = blockIdx.x * blockDim.x + threadIdx.x;
    if (t >= nrows * C4) return;
    int r = t / C4, cc = t % C4;
    ((float4*)dst)[t] = ((const float4*)src)[(size_t)idx[r] * C4 + cc];
}

__global__ void fuse_pi_h(const float* __restrict__ tmpP, const float* __restrict__ Acomb,
                          const int* __restrict__ rel_inds, const float* __restrict__ bias,
                          uint32_t* __restrict__ outh)
{
    const int C4 = EMB / 4;
    int t = blockIdx.x * blockDim.x + threadIdx.x;
    if (t >= N_REL * C4) return;
    int r = t / C4, cc = t % C4;
    int s = rel_inds[r * 3 + 1];
    float4 p = ((const float4*)tmpP)[t];
    float4 a = ((const float4*)Acomb)[(size_t)s * C4 + cc];
    float4 b = ((const float4*)bias)[cc];
    float v0 = fmaxf(p.x + a.x + b.x, 0.f), v1 = fmaxf(p.y + a.y + b.y, 0.f);
    float v2 = fmaxf(p.z + a.z + b.z, 0.f), v3 = fmaxf(p.w + a.w + b.w, 0.f);
    outh[t * 2]     = pack_h2(v0, v1);
    outh[t * 2 + 1] = pack_h2(v2, v3);
}

// BsBo combined layout: row stride 2*EMB floats; Bs = cols [0,200), Bo = cols [200,400)
__global__ void fuse_po_h(const float* __restrict__ BsBo, const float* __restrict__ tmpQ,
                          const int* __restrict__ rel_inds,
                          const float* __restrict__ bias, uint32_t* __restrict__ outh)
{
    const int C4 = EMB / 4;        // 50
    const int RS4 = 2 * EMB / 4;   // 100 float4 per BsBo row
    int t = blockIdx.x * blockDim.x + threadIdx.x;
    if (t >= N_REL * C4) return;
    int r = t / C4, cc = t % C4;
    int s = rel_inds[r * 3 + 1];
    int o = rel_inds[r * 3 + 2];
    float4 q  = ((const float4*)tmpQ)[t];
    float4 bs = ((const float4*)BsBo)[(size_t)s * RS4 + cc];
    float4 bo = ((const float4*)BsBo)[(size_t)o * RS4 + C4 + cc];
    float4 b  = ((const float4*)bias)[cc];
    float v0 = fmaxf(q.x + bs.x + bo.x + b.x, 0.f), v1 = fmaxf(q.y + bs.y + bo.y + b.y, 0.f);
    float v2 = fmaxf(q.z + bs.z + bo.z + b.z, 0.f), v3 = fmaxf(q.w + bs.w + bo.w + b.w, 0.f);
    outh[t * 2]     = pack_h2(v0, v1);
    outh[t * 2 + 1] = pack_h2(v2, v3);
}

// ---------------- host side ----------------
template <typename T>
static T* sym(const void* s)
{
    void* p = nullptr;
    cudaGetSymbolAddress(&p, s);
    return (T*)p;
}

static void set_attrs()
{
    static bool done = false;
    if (!done) {
        cudaFuncSetAttribute(hmma_h<0>, cudaFuncAttributeMaxDynamicSharedMemorySize, SMEM_TOT);
        cudaFuncSetAttribute(hmma_h<1>, cudaFuncAttributeMaxDynamicSharedMemorySize, SMEM_TOT);
        done = true;
    }
}

static void gemmh(const half_t* A, const half_t* W, const float* bias,
                  float* C, half_t* Ch, int M, int N, int K, bool relu)
{
    set_attrs();
    dim3 grid((N + 127) / 128, (M + 127) / 128), block(256);
    hmma_h<0><<<grid, block, SMEM_TOT>>>(A, W, bias, C, Ch, M, N, K,
                                         relu ? 1 : 0, C ? 1 : 0, Ch ? 1 : 0, bias ? 1 : 0);
}

static void gemmh32(const float* A, const half_t* W, const float* bias,
                    float* C, half_t* Ch, int M, int N, int K, bool relu)
{
    set_attrs();
    dim3 grid((N + 127) / 128, (M + 127) / 128), block(256);
    hmma_h<1><<<grid, block, SMEM_TOT>>>(A, W, bias, C, Ch, M, N, K,
                                         relu ? 1 : 0, C ? 1 : 0, Ch ? 1 : 0, bias ? 1 : 0);
}

extern "C" void kernel_launch(void* const* d_in, const int* in_sizes, int n_in,
                              void* d_out, int out_size)
{
    (void)in_sizes; (void)n_in; (void)out_size;

    const float* obj_feats  = (const float*)d_in[1];
    const float* rel_feats  = (const float*)d_in[2];
    const int*   rel_inds   = (const int*)d_in[4];
    const int*   gt_rel     = (const int*)d_in[5];
    const int*   gt_obj     = (const int*)d_in[6];
    const float* obj_embed  = (const float*)d_in[7];
    const float* pred_embed = (const float*)d_in[8];
    const float* Wrs = (const float*)d_in[9];  const float* brs = (const float*)d_in[10];
    const float* Wos = (const float*)d_in[11]; const float* bos = (const float*)d_in[12];
    const float* Wso1= (const float*)d_in[13]; const float* bso1= (const float*)d_in[14];
    const float* Wso2= (const float*)d_in[15]; const float* bso2= (const float*)d_in[16];
    const float* Wsoo= (const float*)d_in[17]; const float* bsoo= (const float*)d_in[18];
    const float* Wp1 = (const float*)d_in[19]; const float* bp1 = (const float*)d_in[20];
    const float* Wp2 = (const float*)d_in[21]; const float* bp2 = (const float*)d_in[22];
    const float* Wpi = (const float*)d_in[23]; const float* bpi = (const float*)d_in[24];
    const float* Wpo1= (const float*)d_in[25]; const float* bpo1= (const float*)d_in[26];
    const float* Wpo2= (const float*)d_in[27]; const float* bpo2= (const float*)d_in[28];

    float* out = (float*)d_out;
    float* o_so_out   = out;                      // [50000,200]
    float* o_pred_out = out + 10000000;           // [200000,200]
    float* o_rel_sem  = out + 50000000;           // [200000,200]
    float* o_obj_sem  = out + 90000000;           // [50000,200]
    float* o_rel_gt   = out + 100000000;          // [51,200]
    float* o_obj_gt   = out + 100010200;          // [151,200]

    half_t *h1r = sym<half_t>(g_h1r_h), *h1o = sym<half_t>(g_h1o_h);
    half_t *pri = sym<half_t>(g_pri_h), *soi = sym<half_t>(g_soi_h);
    half_t *paf = sym<half_t>(g_paf_h), *soo = sym<half_t>(g_soo_h);
    half_t *hpo = sym<half_t>(g_hpo_h);
    half_t *pe = sym<half_t>(g_pe_h), *oe = sym<half_t>(g_oe_h);
    half_t *wrs = sym<half_t>(g_wrs), *wos = sym<half_t>(g_wos);
    half_t *wso1 = sym<half_t>(g_wso1), *wso2 = sym<half_t>(g_wso2);
    half_t *wsoo = sym<half_t>(g_wsoo);
    half_t *wp1 = sym<half_t>(g_wp1), *wp2 = sym<half_t>(g_wp2);
    half_t *wpip = sym<half_t>(g_wpip), *wcmb = sym<half_t>(g_wcmb);
    half_t *w1p = sym<half_t>(g_w1p);
    half_t *wBsBo = sym<half_t>(g_wBsBo);
    half_t *wpo2 = sym<half_t>(g_wpo2);
    float *Acomb = sym<float>(g_Acomb), *tmpP = sym<float>(g_tmpP);
    float *BsBo = sym<float>(g_BsBo), *tmpQ = sym<float>(g_tmpQ);

    // ---- one batched conversion for all weights + embeds (15 segments) ----
    {
        ConvArgs a;
        int off = 0, i = 0;
        auto add = [&](const float* src, half_t* dst, int lds, int rows, int cols) {
            a.seg[i].src = src; a.seg[i].dst = dst; a.seg[i].lds = lds;
            a.seg[i].K = cols; a.seg[i].off = off;
            off += rows * cols; i++;
        };
        add(Wrs, wrs, EMB, EMB, EMB);
        add(Wos, wos, EMB, EMB, EMB);
        add(Wso1, wso1, FEAT, INTER, FEAT);
        add(Wso2, wso2, INTER, EMB, INTER);
        add(Wsoo, wsoo, EMB, EMB, EMB);
        add(Wp1, wp1, FEAT, INTER, FEAT);
        add(Wp2, wp2, INTER, EMB, INTER);
        add(Wpi + EMB, wpip, 600, EMB, EMB);
        add(Wpo1, wBsBo, 600, EMB, EMB);                       // combined rows 0..199 (Bs)
        add(Wpo1 + 2 * EMB, wBsBo + EMB * EMB, 600, EMB, EMB); // combined rows 200..399 (Bo)
        add(Wpo1 + EMB, w1p, 600, EMB, EMB);
        add(Wpo2, wpo2, EMB, EMB, EMB);
        add(pred_embed, pe, EMB, N_PRED, EMB);
        add(obj_embed, oe, EMB, N_CLS, EMB);
        a.nseg = i; a.total = off;
        conv_all<<<(off + 255) / 256, 256>>>(a);
    }
    combine_wpi_h<<<(EMB * EMB + 255) / 256, 256>>>(Wpi, wcmb);

    // ---- semantic tables + gathers ----
    gemmh(pe, wrs, brs, o_rel_gt, nullptr, N_PRED, EMB, EMB, false);
    gemmh(oe, wos, bos, o_obj_gt, nullptr, N_CLS, EMB, EMB, false);
    gather_rows_f4<<<(N_REL * (EMB / 4) + 255) / 256, 256>>>(o_rel_gt, gt_rel, o_rel_sem, N_REL);
    gather_rows_f4<<<(N_OBJ * (EMB / 4) + 255) / 256, 256>>>(o_obj_gt, gt_obj, o_obj_sem, N_OBJ);

    // ---- object path ----
    gemmh32(obj_feats, wso1, bso1, nullptr, h1o, N_OBJ, INTER, FEAT, true);
    gemmh(h1o, wso2, bso2, nullptr, soi, N_OBJ, EMB, INTER, true);
    gemmh(soi, wsoo, bsoo, o_so_out, soo, N_OBJ, EMB, EMB, false);

    // ---- relation path ----
    gemmh32(rel_feats, wp1, bp1, nullptr, h1r, N_REL, INTER, FEAT, true);
    gemmh(h1r, wp2, bp2, nullptr, pri, N_REL, EMB, INTER, true);

    // ---- pred_inter_af (factored concat; obj slice == sub slice index) ----
    gemmh(soi, wcmb, nullptr, Acomb, nullptr, N_OBJ, EMB, EMB, false);
    gemmh(pri, wpip, nullptr, tmpP, nullptr, N_REL, EMB, EMB, false);
    fuse_pi_h<<<(N_REL * (EMB / 4) + 255) / 256, 256>>>(tmpP, Acomb, rel_inds, bpi,
                                                        (uint32_t*)paf);

    // ---- pred_out: Bs+Bo as ONE N=400 GEMM, then fuse + final GEMM ----
    gemmh(soo, wBsBo, nullptr, BsBo, nullptr, N_OBJ, 2 * EMB, EMB, false);
    gemmh(paf, w1p, nullptr, tmpQ, nullptr, N_REL, EMB, EMB, false);
    fuse_po_h<<<(N_REL * (EMB / 4) + 255) / 256, 256>>>(BsBo, tmpQ, rel_inds, bpo1,
                                                        (uint32_t*)hpo);
    gemmh(hpo, wpo2, bpo2, o_pred_out, nullptr, N_REL, EMB, EMB, false);
}